// round 7
// baseline (speedup 1.0000x reference)
#include <cuda_runtime.h>
#include <cstddef>

// ---------------------------------------------------------------------------
// StackSAModuleMSG — tf32 tensor cores, fragment-major smem staging.
// B=4, NB=8192, MB=2048, M=8192, C_IN=64, CIN=67 (K padded to 72).
// Scale 0: r=0.2, NS=16.  Scale 1: r=0.4, NS=32.
//
// Per scale: ballquery -> gemm1(gather fused, stats fused) ->
//            gemm2(BN+ReLU fused on A, stats fused) -> maxpool(BN inline).
// BN finalize is recomputed per-block inside consumers (no tiny kernels).
// ---------------------------------------------------------------------------

#define MTOT 8192
#define NPB  8192

__device__ float g_X0[262144 * 128];
__device__ float g_X1[262144 * 128];
__device__ int   g_idx[8192 * 32];
__device__ float g_sumA[512];   // 4 stages x 128 channels
__device__ float g_sqA[512];

__device__ __forceinline__ unsigned f2tf(float f) {
    unsigned r;
    asm("cvt.rna.tf32.f32 %0, %1;" : "=r"(r) : "f"(f));
    return r;
}

__device__ __forceinline__ void mma_tf32(float* c, const unsigned a0,
                                         const unsigned a1, const unsigned a2,
                                         const unsigned a3, unsigned b0,
                                         unsigned b1) {
    asm volatile(
        "mma.sync.aligned.m16n8k8.row.col.f32.tf32.tf32.f32 "
        "{%0,%1,%2,%3}, {%4,%5,%6,%7}, {%8,%9}, {%0,%1,%2,%3};"
        : "+f"(c[0]), "+f"(c[1]), "+f"(c[2]), "+f"(c[3])
        : "r"(a0), "r"(a1), "r"(a2), "r"(a3), "r"(b0), "r"(b1));
}

// ---------------------------------------------------------------------------
__global__ void zero_stats_all() {
    int t = blockIdx.x * blockDim.x + threadIdx.x;
    if (t < 512) {
        g_sumA[t] = 0.0f;
        g_sqA[t]  = 0.0f;
    }
}

// ---------------------------------------------------------------------------
// Ball query: one warp per query; exact fp32 arithmetic (membership must
// match the reference bit-for-bit). First NS index-order hits, early exit.
// ---------------------------------------------------------------------------
template <int NS>
__global__ void ballquery_kernel(const float* __restrict__ xyz,
                                 const float* __restrict__ newxyz,
                                 float r2, int* __restrict__ idx_out) {
    int gw   = (blockIdx.x * blockDim.x + threadIdx.x) >> 5;
    int lane = threadIdx.x & 31;
    if (gw >= MTOT) return;
    int b = gw >> 11;
    float qx = newxyz[gw * 3 + 0];
    float qy = newxyz[gw * 3 + 1];
    float qz = newxyz[gw * 3 + 2];
    float qq = __fadd_rn(__fadd_rn(__fmul_rn(qx, qx), __fmul_rn(qy, qy)),
                         __fmul_rn(qz, qz));
    const float* P = xyz + (size_t)b * NPB * 3;
    int cnt = 0;
    int first = -1;
    for (int start = 0; start < NPB; start += 32) {
        int i = start + lane;
        float px = P[i * 3 + 0];
        float py = P[i * 3 + 1];
        float pz = P[i * 3 + 2];
        float pp = __fadd_rn(__fadd_rn(__fmul_rn(px, px), __fmul_rn(py, py)),
                             __fmul_rn(pz, pz));
        float dt = __fadd_rn(__fadd_rn(__fmul_rn(qx, px), __fmul_rn(qy, py)),
                             __fmul_rn(qz, pz));
        float d2 = __fsub_rn(__fadd_rn(qq, pp), __fmul_rn(2.0f, dt));
        bool in = d2 < r2;
        unsigned mask = __ballot_sync(0xFFFFFFFFu, in);
        if (mask) {
            if (first < 0) first = start + (__ffs(mask) - 1);
            int pos = cnt + __popc(mask & ((1u << lane) - 1u));
            if (in && pos < NS) idx_out[gw * NS + pos] = i;
            cnt += __popc(mask);
            if (cnt >= NS) break;
        }
    }
    if (cnt == 0) {
        for (int j = lane; j < NS; j += 32) idx_out[gw * NS + j] = -1;
    } else if (cnt < NS) {
        for (int j = cnt + lane; j < NS; j += 32) idx_out[gw * NS + j] = first;
    }
}

// ---------------------------------------------------------------------------
// GEMM1: X0[R,128] = G[R,67] @ W0^T. Block 128x128, 8 warps (4m x 2n),
// warp 32x64. A/W staged in fragment-major order:
//   A: [mtile(8)][ks(9)][lane(32)][reg(4)]   reg = half + 2*quad
//   B: [ntpair(8)][ks(9)][lane(32)][reg(4)]  reg = pair*2 + quad
// Mainloop: 2x LDS.128 (A) + 4x LDS.128 (B) per 16 HMMA.
// ---------------------------------------------------------------------------
#define KS1 9
#define SMEM1B ((9216 + 9216 + 256) * 4)

template <int NS>
__global__ __launch_bounds__(256, 2) void gemm1_tc(
    const float* __restrict__ xyz, const float* __restrict__ feat,
    const float* __restrict__ newxyz, const int* __restrict__ idx,
    const float* __restrict__ w0, float* __restrict__ X0,
    float* __restrict__ sum_out, float* __restrict__ sq_out) {
    extern __shared__ unsigned sh[];
    unsigned* Af = sh;             // 8*9*32*4
    unsigned* Bf = sh + 9216;      // 8*9*32*4
    float* s_sum = (float*)(sh + 18432);
    float* s_sq  = s_sum + 128;
    int tid = threadIdx.x;

    if (tid < 128) { s_sum[tid] = 0.0f; s_sq[tid] = 0.0f; }

    // stage W (fragment order)
    {
        int o  = tid >> 1, lw = tid & 1;
        int nt = o >> 3, gid = o & 7, ntp = nt >> 1, pair = nt & 1;
        const float* wrow = w0 + o * 67;
#pragma unroll
        for (int c = lw * 36; c < lw * 36 + 36; ++c) {
            unsigned v = (c < 67) ? f2tf(wrow[c]) : 0u;
            int ks = c >> 3, c8 = c & 7;
            Bf[(((ntp * KS1 + ks) * 32 + gid * 4 + (c8 & 3)) << 2) +
               pair * 2 + (c8 >> 2)] = v;
        }
    }

    // stage A: gather + center (fragment order)
    int row0 = blockIdx.x * 128;
    {
        int r   = tid >> 1, lw = tid & 1;
        int rg  = row0 + r;
        int m   = rg / NS;
        int p   = idx[rg];
        int mtg = r >> 4, ri = r & 15;
        unsigned* base = Af + ((mtg * KS1) * 32 + (ri & 7) * 4) * 4 + (ri >> 3);
        // put value at column c:
        //   off = (ks*32*4 + t4*4)*... computed below
        if (p < 0) {
#pragma unroll
            for (int c = lw * 36; c < lw * 36 + 36; ++c) {
                int ks = c >> 3, c8 = c & 7;
                base[(ks * 128 + (c8 & 3) * 4) + ((c8 >> 2) << 1)] = 0u;
            }
        } else {
            int gp = ((m >> 11) << 13) + p;
            const float4* frow = (const float4*)(feat + (size_t)gp * 64);
            if (lw == 0) {
                float c0 = xyz[gp * 3 + 0] - newxyz[m * 3 + 0];
                float c1 = xyz[gp * 3 + 1] - newxyz[m * 3 + 1];
                float c2 = xyz[gp * 3 + 2] - newxyz[m * 3 + 2];
                base[0]      = f2tf(c0);
                base[4]      = f2tf(c1);
                base[8]      = f2tf(c2);
#pragma unroll
                for (int f = 0; f < 8; ++f) {
                    float4 v = frow[f];
                    float vv[4] = {v.x, v.y, v.z, v.w};
#pragma unroll
                    for (int e = 0; e < 4; ++e) {
                        int c = 3 + 4 * f + e;
                        int ks = c >> 3, c8 = c & 7;
                        base[(ks * 128 + (c8 & 3) * 4) + ((c8 >> 2) << 1)] =
                            f2tf(vv[e]);
                    }
                }
            } else {
#pragma unroll
                for (int f = 8; f < 16; ++f) {
                    float4 v = frow[f];
                    float vv[4] = {v.x, v.y, v.z, v.w};
#pragma unroll
                    for (int e = 0; e < 4; ++e) {
                        int c = 3 + 4 * f + e;
                        int ks = c >> 3, c8 = c & 7;
                        base[(ks * 128 + (c8 & 3) * 4) + ((c8 >> 2) << 1)] =
                            f2tf(vv[e]);
                    }
                }
#pragma unroll
                for (int c = 67; c < 72; ++c) {
                    int ks = c >> 3, c8 = c & 7;
                    base[(ks * 128 + (c8 & 3) * 4) + ((c8 >> 2) << 1)] = 0u;
                }
            }
        }
    }
    __syncthreads();

    int lane = tid & 31;
    int wid  = tid >> 5;
    int wm = wid & 3, wn = wid >> 2;
    int gid = lane >> 2, t4 = lane & 3;

    float acc[2][8][4];
#pragma unroll
    for (int mt = 0; mt < 2; ++mt)
#pragma unroll
        for (int nt = 0; nt < 8; ++nt)
#pragma unroll
            for (int j = 0; j < 4; ++j) acc[mt][nt][j] = 0.0f;

    const uint4* Aq = (const uint4*)Af + ((wm * 2) * KS1) * 32 + lane;
    const uint4* Bq = (const uint4*)Bf + ((wn * 4) * KS1) * 32 + lane;

#pragma unroll
    for (int ks = 0; ks < KS1; ++ks) {
        uint4 a0 = Aq[ks * 32];
        uint4 a1 = Aq[(KS1 + ks) * 32];
#pragma unroll
        for (int p = 0; p < 4; ++p) {
            uint4 b = Bq[(p * KS1 + ks) * 32];
            mma_tf32(acc[0][2 * p],     a0.x, a0.y, a0.z, a0.w, b.x, b.y);
            mma_tf32(acc[0][2 * p + 1], a0.x, a0.y, a0.z, a0.w, b.z, b.w);
            mma_tf32(acc[1][2 * p],     a1.x, a1.y, a1.z, a1.w, b.x, b.y);
            mma_tf32(acc[1][2 * p + 1], a1.x, a1.y, a1.z, a1.w, b.z, b.w);
        }
    }

#pragma unroll
    for (int mt = 0; mt < 2; ++mt) {
        int rbase = row0 + wm * 32 + mt * 16 + gid;
#pragma unroll
        for (int nt = 0; nt < 8; ++nt) {
            int cc = wn * 64 + nt * 8 + t4 * 2;
            *(float2*)(X0 + (size_t)rbase * 128 + cc) =
                make_float2(acc[mt][nt][0], acc[mt][nt][1]);
            *(float2*)(X0 + (size_t)(rbase + 8) * 128 + cc) =
                make_float2(acc[mt][nt][2], acc[mt][nt][3]);
        }
    }
#pragma unroll
    for (int nt = 0; nt < 8; ++nt) {
#pragma unroll
        for (int j = 0; j < 2; ++j) {
            float v0 = acc[0][nt][j], v1 = acc[0][nt][j + 2];
            float v2 = acc[1][nt][j], v3 = acc[1][nt][j + 2];
            float s = v0 + v1 + v2 + v3;
            float q = v0 * v0 + v1 * v1 + v2 * v2 + v3 * v3;
#pragma unroll
            for (int o = 4; o <= 16; o <<= 1) {
                s += __shfl_xor_sync(0xFFFFFFFFu, s, o);
                q += __shfl_xor_sync(0xFFFFFFFFu, q, o);
            }
            if (gid == 0) {
                int c = wn * 64 + nt * 8 + t4 * 2 + j;
                atomicAdd(&s_sum[c], s);
                atomicAdd(&s_sq[c], q);
            }
        }
    }
    __syncthreads();
    if (tid < 128) {
        atomicAdd(&sum_out[tid], s_sum[tid]);
        atomicAdd(&sq_out[tid], s_sq[tid]);
    }
}

// ---------------------------------------------------------------------------
// GEMM2: X1[R,128] = relu(bn(X0)) @ W1^T, K=128. Block 64x128, 8 warps
// (2m x 4n), warp 32x32. BN finalize computed in-block from stage stats.
//   A: [mtile(4)][ks(16)][lane][4]   B: [ntpair(8)][ks(16)][lane][4]
// ---------------------------------------------------------------------------
#define KS2 16
#define SMEM2B ((8192 + 16384 + 512) * 4)

__global__ __launch_bounds__(256, 2) void gemm2_tc(
    const float* __restrict__ Xin, const float* __restrict__ w1,
    float* __restrict__ Xout, const float* __restrict__ sum_in,
    const float* __restrict__ sq_in, const float* __restrict__ gamma,
    const float* __restrict__ beta, float invR,
    float* __restrict__ sum_out, float* __restrict__ sq_out) {
    extern __shared__ unsigned sh[];
    unsigned* Af = sh;               // 4*16*32*4 = 8192
    unsigned* Bf = sh + 8192;        // 8*16*32*4 = 16384
    float* s_sum = (float*)(sh + 24576);
    float* s_sq  = s_sum + 128;
    float* sc    = s_sq + 128;
    float* sf    = sc + 128;
    int tid = threadIdx.x;

    if (tid < 128) {
        s_sum[tid] = 0.0f;
        s_sq[tid]  = 0.0f;
        float mean = sum_in[tid] * invR;
        float var  = sq_in[tid] * invR - mean * mean;
        float s    = gamma[tid] * rsqrtf(var + 1e-5f);
        sc[tid] = s;
        sf[tid] = fmaf(-mean, s, beta[tid]);
    }
    // stage W
    {
        int o  = tid >> 1, lw = tid & 1;
        int nt = o >> 3, gid = o & 7, ntp = nt >> 1, pair = nt & 1;
        const float* wrow = w1 + o * 128;
#pragma unroll
        for (int c = lw * 64; c < lw * 64 + 64; ++c) {
            int ks = c >> 3, c8 = c & 7;
            Bf[(((ntp * KS2 + ks) * 32 + gid * 4 + (c8 & 3)) << 2) +
               pair * 2 + (c8 >> 2)] = f2tf(wrow[c]);
        }
    }
    __syncthreads();

    // stage A with BN + ReLU
    int row0 = blockIdx.x * 64;
    for (int i = tid; i < 64 * 32; i += 256) {
        int r = i >> 5, kq = (i & 31) << 2;
        float4 v = *(const float4*)(Xin + (size_t)(row0 + r) * 128 + kq);
        int mtg = r >> 4, ri = r & 15;
        int ks = kq >> 3, quad = (kq & 7) >> 2;
        unsigned* base = Af + ((mtg * KS2 + ks) * 32 + (ri & 7) * 4) * 4 +
                         (ri >> 3) + 2 * quad;
        base[0]  = f2tf(fmaxf(fmaf(sc[kq + 0], v.x, sf[kq + 0]), 0.0f));
        base[4]  = f2tf(fmaxf(fmaf(sc[kq + 1], v.y, sf[kq + 1]), 0.0f));
        base[8]  = f2tf(fmaxf(fmaf(sc[kq + 2], v.z, sf[kq + 2]), 0.0f));
        base[12] = f2tf(fmaxf(fmaf(sc[kq + 3], v.w, sf[kq + 3]), 0.0f));
    }
    __syncthreads();

    int lane = tid & 31;
    int wid  = tid >> 5;
    int wm = wid & 1, wn = wid >> 1;
    int gid = lane >> 2, t4 = lane & 3;

    float acc[2][4][4];
#pragma unroll
    for (int mt = 0; mt < 2; ++mt)
#pragma unroll
        for (int nt = 0; nt < 4; ++nt)
#pragma unroll
            for (int j = 0; j < 4; ++j) acc[mt][nt][j] = 0.0f;

    const uint4* Aq = (const uint4*)Af + ((wm * 2) * KS2) * 32 + lane;
    const uint4* Bq = (const uint4*)Bf + ((wn * 2) * KS2) * 32 + lane;

#pragma unroll
    for (int ks = 0; ks < KS2; ++ks) {
        uint4 a0 = Aq[ks * 32];
        uint4 a1 = Aq[(KS2 + ks) * 32];
#pragma unroll
        for (int p = 0; p < 2; ++p) {
            uint4 b = Bq[(p * KS2 + ks) * 32];
            mma_tf32(acc[0][2 * p],     a0.x, a0.y, a0.z, a0.w, b.x, b.y);
            mma_tf32(acc[0][2 * p + 1], a0.x, a0.y, a0.z, a0.w, b.z, b.w);
            mma_tf32(acc[1][2 * p],     a1.x, a1.y, a1.z, a1.w, b.x, b.y);
            mma_tf32(acc[1][2 * p + 1], a1.x, a1.y, a1.z, a1.w, b.z, b.w);
        }
    }

#pragma unroll
    for (int mt = 0; mt < 2; ++mt) {
        int rbase = row0 + wm * 32 + mt * 16 + gid;
#pragma unroll
        for (int nt = 0; nt < 4; ++nt) {
            int cc = wn * 32 + nt * 8 + t4 * 2;
            *(float2*)(Xout + (size_t)rbase * 128 + cc) =
                make_float2(acc[mt][nt][0], acc[mt][nt][1]);
            *(float2*)(Xout + (size_t)(rbase + 8) * 128 + cc) =
                make_float2(acc[mt][nt][2], acc[mt][nt][3]);
        }
    }
#pragma unroll
    for (int nt = 0; nt < 4; ++nt) {
#pragma unroll
        for (int j = 0; j < 2; ++j) {
            float v0 = acc[0][nt][j], v1 = acc[0][nt][j + 2];
            float v2 = acc[1][nt][j], v3 = acc[1][nt][j + 2];
            float s = v0 + v1 + v2 + v3;
            float q = v0 * v0 + v1 * v1 + v2 * v2 + v3 * v3;
#pragma unroll
            for (int o = 4; o <= 16; o <<= 1) {
                s += __shfl_xor_sync(0xFFFFFFFFu, s, o);
                q += __shfl_xor_sync(0xFFFFFFFFu, q, o);
            }
            if (gid == 0) {
                int c = wn * 32 + nt * 8 + t4 * 2 + j;
                atomicAdd(&s_sum[c], s);
                atomicAdd(&s_sq[c], q);
            }
        }
    }
    __syncthreads();
    if (tid < 128) {
        atomicAdd(&sum_out[tid], s_sum[tid]);
        atomicAdd(&sq_out[tid], s_sq[tid]);
    }
}

// ---------------------------------------------------------------------------
// BN (inline finalize) + ReLU + max over NS -> out[:, colBase:colBase+128]
// ---------------------------------------------------------------------------
template <int NS>
__global__ void maxpool_kernel(const float* __restrict__ X,
                               float* __restrict__ out, int colBase,
                               const float* __restrict__ sum_in,
                               const float* __restrict__ sq_in,
                               const float* __restrict__ gamma,
                               const float* __restrict__ beta, float invR) {
    int t = blockIdx.x * blockDim.x + threadIdx.x;
    if (t >= MTOT * 128) return;
    int m = t >> 7;
    int c = t & 127;
    float mean = sum_in[c] * invR;
    float var  = sq_in[c] * invR - mean * mean;
    float s    = gamma[c] * rsqrtf(var + 1e-5f);
    float b    = fmaf(-mean, s, beta[c]);
    float mx = -3.0e38f;
    const float* px = X + (size_t)m * NS * 128 + c;
#pragma unroll
    for (int j = 0; j < NS; ++j) mx = fmaxf(mx, fmaf(s, px[j * 128], b));
    out[(size_t)m * 256 + colBase + c] = fmaxf(mx, 0.0f);
}

__global__ void copy_kernel(const float* __restrict__ src,
                            float* __restrict__ dst, int n) {
    int t = blockIdx.x * blockDim.x + threadIdx.x;
    if (t < n) dst[t] = src[t];
}

// ---------------------------------------------------------------------------
extern "C" void kernel_launch(void* const* d_in, const int* in_sizes, int n_in,
                              void* d_out, int out_size) {
    const float* xyz  = (const float*)d_in[0];
    const float* feat = (const float*)d_in[1];
    const float* nxyz = (const float*)d_in[2];
    const float* w00 = (const float*)d_in[5];
    const float* g00 = (const float*)d_in[6];
    const float* b00 = (const float*)d_in[7];
    const float* w01 = (const float*)d_in[8];
    const float* g01 = (const float*)d_in[9];
    const float* b01 = (const float*)d_in[10];
    const float* w10 = (const float*)d_in[11];
    const float* g10 = (const float*)d_in[12];
    const float* b10 = (const float*)d_in[13];
    const float* w11 = (const float*)d_in[14];
    const float* g11 = (const float*)d_in[15];
    const float* b11 = (const float*)d_in[16];

    float* outBase = (float*)d_out;
    int featOff = out_size - MTOT * 256;
    if (featOff > 0) {
        copy_kernel<<<(featOff + 255) / 256, 256>>>(nxyz, outBase, featOff);
    }
    float* outF = outBase + (featOff > 0 ? featOff : 0);

    cudaFuncSetAttribute(gemm1_tc<16>,
                         cudaFuncAttributeMaxDynamicSharedMemorySize, SMEM1B);
    cudaFuncSetAttribute(gemm1_tc<32>,
                         cudaFuncAttributeMaxDynamicSharedMemorySize, SMEM1B);
    cudaFuncSetAttribute(gemm2_tc,
                         cudaFuncAttributeMaxDynamicSharedMemorySize, SMEM2B);

    float* X0p;
    float* X1p;
    int* idxp;
    float* sumA;
    float* sqA;
    cudaGetSymbolAddress((void**)&X0p, g_X0);
    cudaGetSymbolAddress((void**)&X1p, g_X1);
    cudaGetSymbolAddress((void**)&idxp, g_idx);
    cudaGetSymbolAddress((void**)&sumA, g_sumA);
    cudaGetSymbolAddress((void**)&sqA, g_sqA);

    const float r2_0 = (float)(0.2 * 0.2);
    const float r2_1 = (float)(0.4 * 0.4);

    zero_stats_all<<<2, 256>>>();

    // ---------------- scale 0 (NS=16) ----------------
    {
        const int R = MTOT * 16;  // 131072
        float invR = 1.0f / (float)R;
        ballquery_kernel<16><<<MTOT * 32 / 256, 256>>>(xyz, nxyz, r2_0, idxp);
        gemm1_tc<16><<<R / 128, 256, SMEM1B>>>(xyz, feat, nxyz, idxp, w00,
                                               X0p, sumA + 0, sqA + 0);
        gemm2_tc<<<R / 64, 256, SMEM2B>>>(X0p, w01, X1p, sumA + 0, sqA + 0,
                                          g00, b00, invR, sumA + 128,
                                          sqA + 128);
        maxpool_kernel<16><<<MTOT * 128 / 256, 256>>>(
            X1p, outF, 0, sumA + 128, sqA + 128, g01, b01, invR);
    }

    // ---------------- scale 1 (NS=32) ----------------
    {
        const int R = MTOT * 32;  // 262144
        float invR = 1.0f / (float)R;
        ballquery_kernel<32><<<MTOT * 32 / 256, 256>>>(xyz, nxyz, r2_1, idxp);
        gemm1_tc<32><<<R / 128, 256, SMEM1B>>>(xyz, feat, nxyz, idxp, w10,
                                               X0p, sumA + 256, sqA + 256);
        gemm2_tc<<<R / 64, 256, SMEM2B>>>(X0p, w11, X1p, sumA + 256,
                                          sqA + 256, g10, b10, invR,
                                          sumA + 384, sqA + 384);
        maxpool_kernel<32><<<MTOT * 128 / 256, 256>>>(
            X1p, outF, 128, sumA + 384, sqA + 384, g11, b11, invR);
    }
}

// round 8
// speedup vs baseline: 1.9889x; 1.9889x over previous
#include <cuda_runtime.h>
#include <cstddef>

// ---------------------------------------------------------------------------
// StackSAModuleMSG — tf32 tensor cores, merged-scale launches (4 total).
// B=4, NB=8192, MB=2048, M=8192, C_IN=64, CIN=67 (K padded to 72).
// Scale 0: r=0.2, NS=16 (R=131072).  Scale 1: r=0.4, NS=32 (R=262144).
//
// Launches: ballquery(+zero stats+copy new_xyz) -> gemm1(gather+stats fused)
//           -> gemm2(BN+ReLU fused on A, stats fused, finalize in-block)
//           -> maxpool(BN inline).  Both scales inside each launch.
// ---------------------------------------------------------------------------

#define MTOT 8192
#define NPB  8192

__device__ float g_X0a[131072 * 128];
__device__ float g_X0b[262144 * 128];
__device__ float g_X1a[131072 * 128];
__device__ float g_X1b[262144 * 128];
__device__ int   g_idx0[8192 * 16];
__device__ int   g_idx1[8192 * 32];
__device__ float g_sumA[512];   // slots: 0=g1/s0, 1=g2/s0, 2=g1/s1, 3=g2/s1
__device__ float g_sqA[512];

__device__ __forceinline__ unsigned f2tf(float f) {
    unsigned r;
    asm("cvt.rna.tf32.f32 %0, %1;" : "=r"(r) : "f"(f));
    return r;
}

__device__ __forceinline__ void mma_tf32(float* c, unsigned a0, unsigned a1,
                                         unsigned a2, unsigned a3, unsigned b0,
                                         unsigned b1) {
    asm volatile(
        "mma.sync.aligned.m16n8k8.row.col.f32.tf32.tf32.f32 "
        "{%0,%1,%2,%3}, {%4,%5,%6,%7}, {%8,%9}, {%0,%1,%2,%3};"
        : "+f"(c[0]), "+f"(c[1]), "+f"(c[2]), "+f"(c[3])
        : "r"(a0), "r"(a1), "r"(a2), "r"(a3), "r"(b0), "r"(b1));
}

// ---------------------------------------------------------------------------
// Merged ball query: warp per query, both scales. Exact fp32 arithmetic
// (membership must match reference bit-for-bit). Also folds: stats zeroing
// (block 0) and new_xyz -> out copy (first copyN threads).
// ---------------------------------------------------------------------------
__global__ void ballquery_merged(const float* __restrict__ xyz,
                                 const float* __restrict__ newxyz,
                                 float r2_0, float r2_1,
                                 const float* __restrict__ copySrc,
                                 float* __restrict__ copyDst, int copyN) {
    int tid = threadIdx.x;
    if (blockIdx.x == 0) {
        g_sumA[tid] = 0.0f; g_sumA[tid + 256] = 0.0f;
        g_sqA[tid]  = 0.0f; g_sqA[tid + 256]  = 0.0f;
    }
    int ct = blockIdx.x * 256 + tid;
    if (ct < copyN) copyDst[ct] = copySrc[ct];

    int gw   = (blockIdx.x * 256 + tid) >> 5;
    int lane = tid & 31;
    if (gw >= 2 * MTOT) return;
    int scl = gw >> 13;                 // 0 or 1
    int q   = gw & (MTOT - 1);
    int NS  = scl ? 32 : 16;
    float r2 = scl ? r2_1 : r2_0;
    int* idx_out = (scl ? g_idx1 : g_idx0) + q * NS;

    int b = q >> 11;
    float qx = newxyz[q * 3 + 0];
    float qy = newxyz[q * 3 + 1];
    float qz = newxyz[q * 3 + 2];
    float qq = __fadd_rn(__fadd_rn(__fmul_rn(qx, qx), __fmul_rn(qy, qy)),
                         __fmul_rn(qz, qz));
    const float* P = xyz + (size_t)b * NPB * 3;
    int cnt = 0, first = -1;
    for (int start = 0; start < NPB; start += 32) {
        int i = start + lane;
        float px = P[i * 3 + 0];
        float py = P[i * 3 + 1];
        float pz = P[i * 3 + 2];
        float pp = __fadd_rn(__fadd_rn(__fmul_rn(px, px), __fmul_rn(py, py)),
                             __fmul_rn(pz, pz));
        float dt = __fadd_rn(__fadd_rn(__fmul_rn(qx, px), __fmul_rn(qy, py)),
                             __fmul_rn(qz, pz));
        float d2 = __fsub_rn(__fadd_rn(qq, pp), __fmul_rn(2.0f, dt));
        bool in = d2 < r2;
        unsigned mask = __ballot_sync(0xFFFFFFFFu, in);
        if (mask) {
            if (first < 0) first = start + (__ffs(mask) - 1);
            int pos = cnt + __popc(mask & ((1u << lane) - 1u));
            if (in && pos < NS) idx_out[pos] = i;
            cnt += __popc(mask);
            if (cnt >= NS) break;
        }
    }
    if (cnt == 0) {
        for (int j = lane; j < NS; j += 32) idx_out[j] = -1;
    } else if (cnt < NS) {
        for (int j = cnt + lane; j < NS; j += 32) idx_out[j] = first;
    }
}

// ---------------------------------------------------------------------------
// GEMM1 merged: X0[R,128] = gather(G)[R,67] @ W0^T, both scales.
// 512 threads, 16 warps (4m x 4n), warp tile 32x32, block 128x128.
// Smem pitch 76 (conflict-free frag loads: (row*12+t4) mod 32 distinct).
// Per-channel sum/sumsq fused into epilogue.
// ---------------------------------------------------------------------------
#define PA1 76
#define KP1 72
#define KS1 9
#define SMEM1B ((128 * PA1 * 2 + 256) * 4)

__global__ __launch_bounds__(512, 2) void gemm1_merged(
    const float* __restrict__ xyz, const float* __restrict__ feat,
    const float* __restrict__ newxyz, const float* __restrict__ w00,
    const float* __restrict__ w10) {
    extern __shared__ unsigned sh[];
    unsigned* As = sh;              // [128][76]
    unsigned* Ws = sh + 128 * PA1;  // [128][76]  (W[o][c])
    float* s_sum = (float*)(sh + 2 * 128 * PA1);
    float* s_sq  = s_sum + 128;
    int tid = threadIdx.x;
    int bid = blockIdx.x;
    int scl = bid >= 1024;
    int lb  = scl ? bid - 1024 : bid;
    int nsShift = scl ? 5 : 4;
    const int* idx = scl ? g_idx1 : g_idx0;
    const float* w0 = scl ? w10 : w00;
    float* X0 = scl ? g_X0b : g_X0a;
    float* sum_out = g_sumA + (scl ? 256 : 0);
    float* sq_out  = g_sqA + (scl ? 256 : 0);

    if (tid < 128) { s_sum[tid] = 0.0f; s_sq[tid] = 0.0f; }
    for (int i = tid; i < 128 * KP1; i += 512) {
        int o = i / KP1;
        int c = i - o * KP1;
        Ws[o * PA1 + c] = (c < 67) ? f2tf(w0[o * 67 + c]) : 0u;
    }

    int row0 = lb * 128;
    {
        int r = tid >> 2, lw = tid & 3;
        int rg = row0 + r;
        int m  = rg >> nsShift;
        int p  = idx[rg];
        unsigned* grow = As + r * PA1;
        if (p < 0) {
#pragma unroll
            for (int c = lw * 18; c < lw * 18 + 18; ++c) grow[c] = 0u;
        } else {
            int gp = ((m >> 11) << 13) + p;
            if (lw == 0) {
                grow[0] = f2tf(xyz[gp * 3 + 0] - newxyz[m * 3 + 0]);
                grow[1] = f2tf(xyz[gp * 3 + 1] - newxyz[m * 3 + 1]);
                grow[2] = f2tf(xyz[gp * 3 + 2] - newxyz[m * 3 + 2]);
            }
            const float4* frow = (const float4*)(feat + (size_t)gp * 64);
#pragma unroll
            for (int j = 0; j < 4; ++j) {
                int f = lw + 4 * j;
                float4 v = frow[f];
                grow[3 + 4 * f + 0] = f2tf(v.x);
                grow[3 + 4 * f + 1] = f2tf(v.y);
                grow[3 + 4 * f + 2] = f2tf(v.z);
                grow[3 + 4 * f + 3] = f2tf(v.w);
            }
            if (lw == 3) {
                grow[67] = 0u; grow[68] = 0u; grow[69] = 0u;
                grow[70] = 0u; grow[71] = 0u;
            }
        }
    }
    __syncthreads();

    int lane = tid & 31, wid = tid >> 5;
    int wm = wid & 3, wn = wid >> 2;
    int gid = lane >> 2, t4 = lane & 3;

    float acc[2][4][4];
#pragma unroll
    for (int mt = 0; mt < 2; ++mt)
#pragma unroll
        for (int nt = 0; nt < 4; ++nt)
#pragma unroll
            for (int j = 0; j < 4; ++j) acc[mt][nt][j] = 0.0f;

    const unsigned* Ab = As + (wm * 32 + gid) * PA1 + t4;
    const unsigned* Bb = Ws + (wn * 32 + gid) * PA1 + t4;

#pragma unroll
    for (int ks = 0; ks < KS1; ++ks) {
        int k0 = ks * 8;
        unsigned a[2][4];
#pragma unroll
        for (int mt = 0; mt < 2; ++mt) {
            const unsigned* ap = Ab + mt * 16 * PA1 + k0;
            a[mt][0] = ap[0];
            a[mt][1] = ap[8 * PA1];
            a[mt][2] = ap[4];
            a[mt][3] = ap[8 * PA1 + 4];
        }
#pragma unroll
        for (int nt = 0; nt < 4; ++nt) {
            const unsigned* bp = Bb + nt * 8 * PA1 + k0;
            unsigned b0 = bp[0], b1 = bp[4];
            mma_tf32(acc[0][nt], a[0][0], a[0][1], a[0][2], a[0][3], b0, b1);
            mma_tf32(acc[1][nt], a[1][0], a[1][1], a[1][2], a[1][3], b0, b1);
        }
    }

#pragma unroll
    for (int mt = 0; mt < 2; ++mt) {
        int rbase = row0 + wm * 32 + mt * 16 + gid;
#pragma unroll
        for (int nt = 0; nt < 4; ++nt) {
            int cc = wn * 32 + nt * 8 + t4 * 2;
            *(float2*)(X0 + (size_t)rbase * 128 + cc) =
                make_float2(acc[mt][nt][0], acc[mt][nt][1]);
            *(float2*)(X0 + (size_t)(rbase + 8) * 128 + cc) =
                make_float2(acc[mt][nt][2], acc[mt][nt][3]);
        }
    }
#pragma unroll
    for (int nt = 0; nt < 4; ++nt) {
#pragma unroll
        for (int j = 0; j < 2; ++j) {
            float v0 = acc[0][nt][j], v1 = acc[0][nt][j + 2];
            float v2 = acc[1][nt][j], v3 = acc[1][nt][j + 2];
            float s = v0 + v1 + v2 + v3;
            float q = v0 * v0 + v1 * v1 + v2 * v2 + v3 * v3;
#pragma unroll
            for (int o = 4; o <= 16; o <<= 1) {
                s += __shfl_xor_sync(0xFFFFFFFFu, s, o);
                q += __shfl_xor_sync(0xFFFFFFFFu, q, o);
            }
            if (gid == 0) {
                int c = wn * 32 + nt * 8 + t4 * 2 + j;
                atomicAdd(&s_sum[c], s);
                atomicAdd(&s_sq[c], q);
            }
        }
    }
    __syncthreads();
    if (tid < 128) {
        atomicAdd(&sum_out[tid], s_sum[tid]);
        atomicAdd(&sq_out[tid], s_sq[tid]);
    }
}

// ---------------------------------------------------------------------------
// GEMM2 merged: X1[R,128] = relu(bn(X0)) @ W1^T, K=128, both scales.
// 512 threads, 16 warps (4m x 4n), warp 32x32, block 128x128, pitch 132
// ((row*4+t4) mod 32 distinct). BN finalize in-block; stats fused.
// ---------------------------------------------------------------------------
#define PA2 132
#define KS2 16
#define SMEM2B ((128 * PA2 * 2 + 512) * 4)

__global__ __launch_bounds__(512) void gemm2_merged(
    const float* __restrict__ w01, const float* __restrict__ w11,
    const float* __restrict__ g00, const float* __restrict__ b00,
    const float* __restrict__ g10, const float* __restrict__ b10,
    float invR0, float invR1) {
    extern __shared__ unsigned sh[];
    unsigned* As = sh;               // [128][132]
    unsigned* Ws = sh + 128 * PA2;   // [128][132]
    float* s_sum = (float*)(sh + 2 * 128 * PA2);
    float* s_sq  = s_sum + 128;
    float* sc    = s_sq + 128;
    float* sf    = sc + 128;
    int tid = threadIdx.x;
    int bid = blockIdx.x;
    int scl = bid >= 1024;
    int lb  = scl ? bid - 1024 : bid;
    const float* Xin = scl ? g_X0b : g_X0a;
    float* Xout = scl ? g_X1b : g_X1a;
    const float* w1 = scl ? w11 : w01;
    const float* gamma = scl ? g10 : g00;
    const float* beta  = scl ? b10 : b00;
    float invR = scl ? invR1 : invR0;
    const float* sum_in = g_sumA + (scl ? 256 : 0);
    const float* sq_in  = g_sqA + (scl ? 256 : 0);
    float* sum_out = g_sumA + (scl ? 384 : 128);
    float* sq_out  = g_sqA + (scl ? 384 : 128);

    if (tid < 128) {
        s_sum[tid] = 0.0f;
        s_sq[tid]  = 0.0f;
        float mean = sum_in[tid] * invR;
        float var  = sq_in[tid] * invR - mean * mean;
        float s    = gamma[tid] * rsqrtf(var + 1e-5f);
        sc[tid] = s;
        sf[tid] = fmaf(-mean, s, beta[tid]);
    }
    for (int i = tid; i < 128 * 128; i += 512) {
        int o = i >> 7, k = i & 127;
        Ws[o * PA2 + k] = f2tf(w1[i]);
    }
    __syncthreads();

    int row0 = lb * 128;
    for (int i = tid; i < 128 * 32; i += 512) {
        int r = i >> 5, kq = (i & 31) << 2;
        float4 v = *(const float4*)(Xin + (size_t)(row0 + r) * 128 + kq);
        uint4 u;
        u.x = f2tf(fmaxf(fmaf(sc[kq + 0], v.x, sf[kq + 0]), 0.0f));
        u.y = f2tf(fmaxf(fmaf(sc[kq + 1], v.y, sf[kq + 1]), 0.0f));
        u.z = f2tf(fmaxf(fmaf(sc[kq + 2], v.z, sf[kq + 2]), 0.0f));
        u.w = f2tf(fmaxf(fmaf(sc[kq + 3], v.w, sf[kq + 3]), 0.0f));
        *(uint4*)(As + r * PA2 + kq) = u;
    }
    __syncthreads();

    int lane = tid & 31, wid = tid >> 5;
    int wm = wid & 3, wn = wid >> 2;
    int gid = lane >> 2, t4 = lane & 3;

    float acc[2][4][4];
#pragma unroll
    for (int mt = 0; mt < 2; ++mt)
#pragma unroll
        for (int nt = 0; nt < 4; ++nt)
#pragma unroll
            for (int j = 0; j < 4; ++j) acc[mt][nt][j] = 0.0f;

    const unsigned* Ab = As + (wm * 32 + gid) * PA2 + t4;
    const unsigned* Bb = Ws + (wn * 32 + gid) * PA2 + t4;

#pragma unroll
    for (int ks = 0; ks < KS2; ++ks) {
        int k0 = ks * 8;
        unsigned a[2][4];
#pragma unroll
        for (int mt = 0; mt < 2; ++mt) {
            const unsigned* ap = Ab + mt * 16 * PA2 + k0;
            a[mt][0] = ap[0];
            a[mt][1] = ap[8 * PA2];
            a[mt][2] = ap[4];
            a[mt][3] = ap[8 * PA2 + 4];
        }
#pragma unroll
        for (int nt = 0; nt < 4; ++nt) {
            const unsigned* bp = Bb + nt * 8 * PA2 + k0;
            unsigned b0 = bp[0], b1 = bp[4];
            mma_tf32(acc[0][nt], a[0][0], a[0][1], a[0][2], a[0][3], b0, b1);
            mma_tf32(acc[1][nt], a[1][0], a[1][1], a[1][2], a[1][3], b0, b1);
        }
    }

#pragma unroll
    for (int mt = 0; mt < 2; ++mt) {
        int rbase = row0 + wm * 32 + mt * 16 + gid;
#pragma unroll
        for (int nt = 0; nt < 4; ++nt) {
            int cc = wn * 32 + nt * 8 + t4 * 2;
            *(float2*)(Xout + (size_t)rbase * 128 + cc) =
                make_float2(acc[mt][nt][0], acc[mt][nt][1]);
            *(float2*)(Xout + (size_t)(rbase + 8) * 128 + cc) =
                make_float2(acc[mt][nt][2], acc[mt][nt][3]);
        }
    }
#pragma unroll
    for (int nt = 0; nt < 4; ++nt) {
#pragma unroll
        for (int j = 0; j < 2; ++j) {
            float v0 = acc[0][nt][j], v1 = acc[0][nt][j + 2];
            float v2 = acc[1][nt][j], v3 = acc[1][nt][j + 2];
            float s = v0 + v1 + v2 + v3;
            float q = v0 * v0 + v1 * v1 + v2 * v2 + v3 * v3;
#pragma unroll
            for (int o = 4; o <= 16; o <<= 1) {
                s += __shfl_xor_sync(0xFFFFFFFFu, s, o);
                q += __shfl_xor_sync(0xFFFFFFFFu, q, o);
            }
            if (gid == 0) {
                int c = wn * 32 + nt * 8 + t4 * 2 + j;
                atomicAdd(&s_sum[c], s);
                atomicAdd(&s_sq[c], q);
            }
        }
    }
    __syncthreads();
    if (tid < 128) {
        atomicAdd(&sum_out[tid], s_sum[tid]);
        atomicAdd(&sq_out[tid], s_sq[tid]);
    }
}

// ---------------------------------------------------------------------------
// Merged maxpool: BN (inline finalize) + ReLU + max over NS, both scales.
// ---------------------------------------------------------------------------
__global__ void maxpool_merged(float* __restrict__ out,
                               const float* __restrict__ g01,
                               const float* __restrict__ b01,
                               const float* __restrict__ g11,
                               const float* __restrict__ b11,
                               float invR0, float invR1) {
    int t = blockIdx.x * blockDim.x + threadIdx.x;
    int scl = t >= MTOT * 128;
    int tt = t - scl * MTOT * 128;
    int m = tt >> 7;
    int c = tt & 127;
    int NS = scl ? 32 : 16;
    const float* X = scl ? g_X1b : g_X1a;
    const float* sum_in = g_sumA + (scl ? 384 : 128);
    const float* sq_in  = g_sqA + (scl ? 384 : 128);
    const float* gamma = scl ? g11 : g01;
    const float* beta  = scl ? b11 : b01;
    float invR = scl ? invR1 : invR0;

    float mean = sum_in[c] * invR;
    float var  = sq_in[c] * invR - mean * mean;
    float s    = gamma[c] * rsqrtf(var + 1e-5f);
    float b    = fmaf(-mean, s, beta[c]);
    float mx = -3.0e38f;
    const float* px = X + (size_t)m * NS * 128 + c;
#pragma unroll 8
    for (int j = 0; j < NS; ++j) mx = fmaxf(mx, fmaf(s, px[j * 128], b));
    out[(size_t)m * 256 + (scl ? 128 : 0) + c] = fmaxf(mx, 0.0f);
}

// ---------------------------------------------------------------------------
extern "C" void kernel_launch(void* const* d_in, const int* in_sizes, int n_in,
                              void* d_out, int out_size) {
    const float* xyz  = (const float*)d_in[0];
    const float* feat = (const float*)d_in[1];
    const float* nxyz = (const float*)d_in[2];
    const float* w00 = (const float*)d_in[5];
    const float* g00 = (const float*)d_in[6];
    const float* b00 = (const float*)d_in[7];
    const float* w01 = (const float*)d_in[8];
    const float* g01 = (const float*)d_in[9];
    const float* b01 = (const float*)d_in[10];
    const float* w10 = (const float*)d_in[11];
    const float* g10 = (const float*)d_in[12];
    const float* b10 = (const float*)d_in[13];
    const float* w11 = (const float*)d_in[14];
    const float* g11 = (const float*)d_in[15];
    const float* b11 = (const float*)d_in[16];

    float* outBase = (float*)d_out;
    int featOff = out_size - MTOT * 256;
    if (featOff < 0) featOff = 0;
    float* outF = outBase + featOff;

    cudaFuncSetAttribute(gemm1_merged,
                         cudaFuncAttributeMaxDynamicSharedMemorySize, SMEM1B);
    cudaFuncSetAttribute(gemm2_merged,
                         cudaFuncAttributeMaxDynamicSharedMemorySize, SMEM2B);

    const float r2_0 = (float)(0.2 * 0.2);
    const float r2_1 = (float)(0.4 * 0.4);
    const float invR0 = 1.0f / 131072.0f;
    const float invR1 = 1.0f / 262144.0f;

    // 1) ballquery both scales + zero stats + copy new_xyz to output head
    ballquery_merged<<<2048, 256>>>(xyz, nxyz, r2_0, r2_1, nxyz, outBase,
                                    featOff);
    // 2) gemm1 both scales (1024 + 2048 blocks)
    gemm1_merged<<<3072, 512, SMEM1B>>>(xyz, feat, nxyz, w00, w10);
    // 3) gemm2 both scales
    gemm2_merged<<<3072, 512, SMEM2B>>>(w01, w11, g00, b00, g10, b10, invR0,
                                        invR1);
    // 4) maxpool both scales
    maxpool_merged<<<2 * MTOT * 128 / 256, 256>>>(outF, g01, b01, g11, b11,
                                                  invR0, invR1);
}